// round 11
// baseline (speedup 1.0000x reference)
#include <cuda_runtime.h>
#include <cuda_fp16.h>

// SpatialTransformer: out[b,c,z,y,x] = trilinear_sample(src[b,c], (x+fx, y+fy, z+fz))
// with zero padding (reference normalization cancels exactly: pos = idx + flow).
//
// R10: half2-interleaved scratch (R9) + fused x-pair gather:
//  per (z,y) corner row, ONE aligned LDG.64 covers both x corners {E,E+1},
//  plus a predicated LDG.32 at E+2 for odd px0 (50% of lanes).
//  Weights for the window positions are 3 per-voxel selects (q0,q1,q2).

#define Dd 160
#define Hh 192
#define Ww 160
#define Bb 2
#define Cc 2

#define NVv (Dd * Hh * Ww)          // 4,915,200
#define HWw (Hh * Ww)

// 2 * 4,915,200 * 4B = 39.3 MB scratch (static device allocation: legal)
__device__ __half2 g_srcI[(size_t)Bb * NVv];

__global__ __launch_bounds__(256) void interleave_kernel(const float* __restrict__ src)
{
    // 4 voxels per thread
    int t = blockIdx.x * blockDim.x + threadIdx.x;
    constexpr int NT = Bb * NVv / 4;
    if (t >= NT) return;
    constexpr int NVq = NVv / 4;
    int b  = t / NVq;
    int v4 = (t - b * NVq) * 4;

    const float* s = src + (size_t)b * (Cc * NVv) + v4;
    float4 c0 = __ldg(reinterpret_cast<const float4*>(s));
    float4 c1 = __ldg(reinterpret_cast<const float4*>(s + NVv));

    __half2 h0 = __floats2half2_rn(c0.x, c1.x);
    __half2 h1 = __floats2half2_rn(c0.y, c1.y);
    __half2 h2 = __floats2half2_rn(c0.z, c1.z);
    __half2 h3 = __floats2half2_rn(c0.w, c1.w);

    uint4 pack;
    pack.x = *reinterpret_cast<unsigned int*>(&h0);
    pack.y = *reinterpret_cast<unsigned int*>(&h1);
    pack.z = *reinterpret_cast<unsigned int*>(&h2);
    pack.w = *reinterpret_cast<unsigned int*>(&h3);

    *reinterpret_cast<uint4*>(&g_srcI[(size_t)b * NVv + v4]) = pack;
}

__global__ __launch_bounds__(256) void st_kernel(
    const float* __restrict__ flow,  // [B, 3, D, H, W]
    float* __restrict__ out)         // [B, C, D, H, W]
{
    constexpr int NV = NVv;
    constexpr int HW = HWw;
    constexpr int NTOT = Bb * NV;

    int t = blockIdx.x * blockDim.x + threadIdx.x;
    if (t >= NTOT) return;

    int b = t / NV;
    int v = t - b * NV;                 // lane-consecutive in x
    int x = v % Ww;
    int y = (v / Ww) % Hh;
    int z = v / HW;

    const float* fbase = flow + b * (3 * NV) + v;
    float fx = __ldg(fbase);
    float fy = __ldg(fbase + NV);
    float fz = __ldg(fbase + 2 * NV);

    float px = (float)x + fx;
    float py = (float)y + fy;
    float pz = (float)z + fz;

    float xf = floorf(px), yf = floorf(py), zf = floorf(pz);
    float ax = px - xf, ay = py - yf, az = pz - zf;
    int ix0 = (int)xf, iy0 = (int)yf, iz0 = (int)zf;
    int ix1 = ix0 + 1, iy1 = iy0 + 1, iz1 = iz0 + 1;

    // y/z per-axis weights, zeroed for OOB corners (zero padding)
    float wy0 = (iy0 >= 0 && iy0 < Hh) ? (1.0f - ay) : 0.0f;
    float wy1 = (iy1 >= 0 && iy1 < Hh) ? ay          : 0.0f;
    float wz0 = (iz0 >= 0 && iz0 < Dd) ? (1.0f - az) : 0.0f;
    float wz1 = (iz1 >= 0 && iz1 < Dd) ? az          : 0.0f;

    // x weights, OOB-zeroed
    float wx0 = (ix0 >= 0 && ix0 < Ww) ? (1.0f - ax) : 0.0f;
    float wx1 = (ix1 >= 0 && ix1 < Ww) ? ax          : 0.0f;

    // clamped pair base px0 in [0, W-2]; (u0,u1) = weights for (v[px0], v[px0+1])
    //   ix0 == -1  -> pair (v[0],v[1]),   contrib = wx1*v[0]   -> u0=wx1, u1=0
    //   ix0 == W-1 -> pair (v[W-2],v[W-1]), contrib = wx0*v[W-1] -> u0=0, u1=wx0
    //   deeper OOB -> both zero
    int px0 = min(max(ix0, 0), Ww - 2);
    float u0 = (ix0 < 0) ? wx1 : ((ix0 > Ww - 2) ? 0.0f : wx0);
    float u1 = (ix0 < 0) ? 0.0f : ((ix0 > Ww - 2) ? wx0 : wx1);

    // aligned 2-voxel window [E, E+1]; j = px0 parity
    int E = px0 & ~1;
    int j = px0 & 1;
    float q0 = j ? 0.0f : u0;   // weight for v[E]
    float q1 = j ? u0   : u1;   // weight for v[E+1]
    float q2 = j ? u1   : 0.0f; // weight for v[E+2] (loaded only when j)

    // clamped z/y rows
    int cy0 = min(max(iy0, 0), Hh - 1);
    int cy1 = min(max(iy1, 0), Hh - 1);
    int cz0 = min(max(iz0, 0), Dd - 1);
    int cz1 = min(max(iz1, 0), Dd - 1);

    int oz0 = cz0 * HW, oz1 = cz1 * HW;
    int oy0 = cy0 * Ww, oy1 = cy1 * Ww;

    int rows[4] = {oz0 + oy0, oz0 + oy1, oz1 + oy0, oz1 + oy1};
    float wr[4] = {wz0 * wy0, wz0 * wy1, wz1 * wy0, wz1 * wy1};

    const __half2* sb = g_srcI + (size_t)b * NV;   // interleaved channels, 4 B/voxel

    __half2 hzero = __float2half2_rn(0.0f);

    float a0 = 0.0f, a1 = 0.0f;
#pragma unroll
    for (int r = 0; r < 4; ++r) {
        const __half2* rp = sb + rows[r] + E;      // 8B-aligned (E even, rows even)
        uint2 p = __ldg(reinterpret_cast<const uint2*>(rp));
        __half2 hE  = *reinterpret_cast<__half2*>(&p.x);
        __half2 hE1 = *reinterpret_cast<__half2*>(&p.y);
        __half2 hE2 = j ? __ldg(rp + 2) : hzero;   // predicated, 50% of lanes

        float2 eE  = __half22float2(hE);
        float2 eE1 = __half22float2(hE1);
        float2 eE2 = __half22float2(hE2);

        float r0 = q0 * eE.x;
        r0 = fmaf(q1, eE1.x, r0);
        r0 = fmaf(q2, eE2.x, r0);
        float r1 = q0 * eE.y;
        r1 = fmaf(q1, eE1.y, r1);
        r1 = fmaf(q2, eE2.y, r1);

        a0 = fmaf(wr[r], r0, a0);
        a1 = fmaf(wr[r], r1, a1);
    }

    float* obase = out + (size_t)b * (Cc * NV) + v;
    obase[0]  = a0;
    obase[NV] = a1;
}

extern "C" void kernel_launch(void* const* d_in, const int* in_sizes, int n_in,
                              void* d_out, int out_size) {
    const float* src  = (const float*)d_in[0];
    const float* flow = (const float*)d_in[1];
    float* out = (float*)d_out;

    constexpr int NTOT = Bb * NVv;
    int threads = 256;

    int blocks_pre = (NTOT / 4 + threads - 1) / threads;
    interleave_kernel<<<blocks_pre, threads>>>(src);

    int blocks = (NTOT + threads - 1) / threads;
    st_kernel<<<blocks, threads>>>(flow, out);
}

// round 12
// speedup vs baseline: 1.1270x; 1.1270x over previous
#include <cuda_runtime.h>
#include <cuda_fp16.h>

// SpatialTransformer: out[b,c,z,y,x] = trilinear_sample(src[b,c], (x+fx, y+fy, z+fz))
// with zero padding (reference normalization cancels exactly: pos = idx + flow).
//
// R11: half2-interleaved scratch (R9) + batch-pair per thread:
//  each thread handles voxel (x,y,z) for BOTH batches -> 16 scalar half2
//  gathers in flight (max MLP), shared index math, lanes stay 4B-consecutive.

#define Dd 160
#define Hh 192
#define Ww 160
#define Bb 2
#define Cc 2

#define NVv (Dd * Hh * Ww)          // 4,915,200
#define HWw (Hh * Ww)

// 2 * 4,915,200 * 4B = 39.3 MB scratch (static device allocation: legal)
__device__ __half2 g_srcI[(size_t)Bb * NVv];

__global__ __launch_bounds__(256) void interleave_kernel(const float* __restrict__ src)
{
    // 4 voxels per thread
    int t = blockIdx.x * blockDim.x + threadIdx.x;
    constexpr int NT = Bb * NVv / 4;
    if (t >= NT) return;
    constexpr int NVq = NVv / 4;
    int b  = t / NVq;
    int v4 = (t - b * NVq) * 4;

    const float* s = src + (size_t)b * (Cc * NVv) + v4;
    float4 c0 = __ldg(reinterpret_cast<const float4*>(s));
    float4 c1 = __ldg(reinterpret_cast<const float4*>(s + NVv));

    __half2 h0 = __floats2half2_rn(c0.x, c1.x);
    __half2 h1 = __floats2half2_rn(c0.y, c1.y);
    __half2 h2 = __floats2half2_rn(c0.z, c1.z);
    __half2 h3 = __floats2half2_rn(c0.w, c1.w);

    uint4 pack;
    pack.x = *reinterpret_cast<unsigned int*>(&h0);
    pack.y = *reinterpret_cast<unsigned int*>(&h1);
    pack.z = *reinterpret_cast<unsigned int*>(&h2);
    pack.w = *reinterpret_cast<unsigned int*>(&h3);

    *reinterpret_cast<uint4*>(&g_srcI[(size_t)b * NVv + v4]) = pack;
}

// per-batch corner computation: offsets (8) + weights (8) from flow at voxel v
struct Corners {
    int   o[8];
    float w[8];
};

__device__ __forceinline__ Corners make_corners(int x, int y, int z,
                                                float fx, float fy, float fz)
{
    constexpr int HW = HWw;
    Corners c;

    float px = (float)x + fx;
    float py = (float)y + fy;
    float pz = (float)z + fz;

    float xf = floorf(px), yf = floorf(py), zf = floorf(pz);
    float ax = px - xf, ay = py - yf, az = pz - zf;
    int ix0 = (int)xf, iy0 = (int)yf, iz0 = (int)zf;
    int ix1 = ix0 + 1, iy1 = iy0 + 1, iz1 = iz0 + 1;

    float wx0 = (ix0 >= 0 && ix0 < Ww) ? (1.0f - ax) : 0.0f;
    float wx1 = (ix1 >= 0 && ix1 < Ww) ? ax          : 0.0f;
    float wy0 = (iy0 >= 0 && iy0 < Hh) ? (1.0f - ay) : 0.0f;
    float wy1 = (iy1 >= 0 && iy1 < Hh) ? ay          : 0.0f;
    float wz0 = (iz0 >= 0 && iz0 < Dd) ? (1.0f - az) : 0.0f;
    float wz1 = (iz1 >= 0 && iz1 < Dd) ? az          : 0.0f;

    int cx0 = min(max(ix0, 0), Ww - 1);
    int cx1 = min(max(ix1, 0), Ww - 1);
    int cy0 = min(max(iy0, 0), Hh - 1);
    int cy1 = min(max(iy1, 0), Hh - 1);
    int cz0 = min(max(iz0, 0), Dd - 1);
    int cz1 = min(max(iz1, 0), Dd - 1);

    int oz0 = cz0 * HW, oz1 = cz1 * HW;
    int oy0 = cy0 * Ww, oy1 = cy1 * Ww;

    c.o[0] = oz0 + oy0 + cx0;
    c.o[1] = oz0 + oy0 + cx1;
    c.o[2] = oz0 + oy1 + cx0;
    c.o[3] = oz0 + oy1 + cx1;
    c.o[4] = oz1 + oy0 + cx0;
    c.o[5] = oz1 + oy0 + cx1;
    c.o[6] = oz1 + oy1 + cx0;
    c.o[7] = oz1 + oy1 + cx1;

    float wz0y0 = wz0 * wy0;
    float wz0y1 = wz0 * wy1;
    float wz1y0 = wz1 * wy0;
    float wz1y1 = wz1 * wy1;

    c.w[0] = wz0y0 * wx0;
    c.w[1] = wz0y0 * wx1;
    c.w[2] = wz0y1 * wx0;
    c.w[3] = wz0y1 * wx1;
    c.w[4] = wz1y0 * wx0;
    c.w[5] = wz1y0 * wx1;
    c.w[6] = wz1y1 * wx0;
    c.w[7] = wz1y1 * wx1;
    return c;
}

__global__ __launch_bounds__(256) void st_kernel(
    const float* __restrict__ flow,  // [B, 3, D, H, W]
    float* __restrict__ out)         // [B, C, D, H, W]
{
    constexpr int NV = NVv;
    constexpr int HW = HWw;

    int v = blockIdx.x * blockDim.x + threadIdx.x;   // voxel, lane-consecutive in x
    if (v >= NV) return;

    int x = v % Ww;
    int y = (v / Ww) % Hh;
    int z = v / HW;

    // flow for both batches
    const float* f0 = flow + v;
    const float* f1 = flow + 3 * NV + v;
    float fx0 = __ldg(f0), fy0 = __ldg(f0 + NV), fz0 = __ldg(f0 + 2 * NV);
    float fx1 = __ldg(f1), fy1 = __ldg(f1 + NV), fz1 = __ldg(f1 + 2 * NV);

    Corners cA = make_corners(x, y, z, fx0, fy0, fz0);
    Corners cB = make_corners(x, y, z, fx1, fy1, fz1);

    const __half2* sA = g_srcI;        // batch 0
    const __half2* sB = g_srcI + NV;   // batch 1

    // issue all 16 gathers for max MLP
    __half2 hA[8], hB[8];
#pragma unroll
    for (int i = 0; i < 8; ++i) hA[i] = __ldg(sA + cA.o[i]);
#pragma unroll
    for (int i = 0; i < 8; ++i) hB[i] = __ldg(sB + cB.o[i]);

    float a0 = 0.f, a1 = 0.f, b0 = 0.f, b1 = 0.f;
#pragma unroll
    for (int i = 0; i < 8; ++i) {
        float2 eA = __half22float2(hA[i]);
        float2 eB = __half22float2(hB[i]);
        a0 = fmaf(cA.w[i], eA.x, a0);
        a1 = fmaf(cA.w[i], eA.y, a1);
        b0 = fmaf(cB.w[i], eB.x, b0);
        b1 = fmaf(cB.w[i], eB.y, b1);
    }

    out[v]               = a0;
    out[v + NV]          = a1;
    out[v + 2 * NV]      = b0;
    out[v + 3 * NV]      = b1;
}

extern "C" void kernel_launch(void* const* d_in, const int* in_sizes, int n_in,
                              void* d_out, int out_size) {
    const float* src  = (const float*)d_in[0];
    const float* flow = (const float*)d_in[1];
    float* out = (float*)d_out;

    int threads = 256;

    constexpr int NTOT = Bb * NVv;
    int blocks_pre = (NTOT / 4 + threads - 1) / threads;
    interleave_kernel<<<blocks_pre, threads>>>(src);

    int blocks = (NVv + threads - 1) / threads;
    st_kernel<<<blocks, threads>>>(flow, out);
}

// round 13
// speedup vs baseline: 1.1595x; 1.0289x over previous
#include <cuda_runtime.h>
#include <cuda_fp16.h>

// SpatialTransformer: out[b,c,z,y,x] = trilinear_sample(src[b,c], (x+fx, y+fy, z+fz))
// with zero padding (reference normalization cancels exactly: pos = idx + flow).
//
// R12: half2-interleaved scratch + 4 samples per thread (y-pair x batch-pair):
//  32 scalar half2 gathers in flight per thread, lanes stay 4B-consecutive in x.

#define Dd 160
#define Hh 192
#define Ww 160
#define Bb 2
#define Cc 2

#define NVv (Dd * Hh * Ww)          // 4,915,200
#define HWw (Hh * Ww)

// 2 * 4,915,200 * 4B = 39.3 MB scratch (static device allocation: legal)
__device__ __half2 g_srcI[(size_t)Bb * NVv];

__global__ __launch_bounds__(256) void interleave_kernel(const float* __restrict__ src)
{
    // 4 voxels per thread
    int t = blockIdx.x * blockDim.x + threadIdx.x;
    constexpr int NT = Bb * NVv / 4;
    if (t >= NT) return;
    constexpr int NVq = NVv / 4;
    int b  = t / NVq;
    int v4 = (t - b * NVq) * 4;

    const float* s = src + (size_t)b * (Cc * NVv) + v4;
    float4 c0 = __ldg(reinterpret_cast<const float4*>(s));
    float4 c1 = __ldg(reinterpret_cast<const float4*>(s + NVv));

    __half2 h0 = __floats2half2_rn(c0.x, c1.x);
    __half2 h1 = __floats2half2_rn(c0.y, c1.y);
    __half2 h2 = __floats2half2_rn(c0.z, c1.z);
    __half2 h3 = __floats2half2_rn(c0.w, c1.w);

    uint4 pack;
    pack.x = *reinterpret_cast<unsigned int*>(&h0);
    pack.y = *reinterpret_cast<unsigned int*>(&h1);
    pack.z = *reinterpret_cast<unsigned int*>(&h2);
    pack.w = *reinterpret_cast<unsigned int*>(&h3);

    *reinterpret_cast<uint4*>(&g_srcI[(size_t)b * NVv + v4]) = pack;
}

// corner offsets (8) + weights (8) for one sample
struct Corners {
    int   o[8];
    float w[8];
};

__device__ __forceinline__ Corners make_corners(int x, int y, int z,
                                                float fx, float fy, float fz)
{
    constexpr int HW = HWw;
    Corners c;

    float px = (float)x + fx;
    float py = (float)y + fy;
    float pz = (float)z + fz;

    float xf = floorf(px), yf = floorf(py), zf = floorf(pz);
    float ax = px - xf, ay = py - yf, az = pz - zf;
    int ix0 = (int)xf, iy0 = (int)yf, iz0 = (int)zf;
    int ix1 = ix0 + 1, iy1 = iy0 + 1, iz1 = iz0 + 1;

    float wx0 = (ix0 >= 0 && ix0 < Ww) ? (1.0f - ax) : 0.0f;
    float wx1 = (ix1 >= 0 && ix1 < Ww) ? ax          : 0.0f;
    float wy0 = (iy0 >= 0 && iy0 < Hh) ? (1.0f - ay) : 0.0f;
    float wy1 = (iy1 >= 0 && iy1 < Hh) ? ay          : 0.0f;
    float wz0 = (iz0 >= 0 && iz0 < Dd) ? (1.0f - az) : 0.0f;
    float wz1 = (iz1 >= 0 && iz1 < Dd) ? az          : 0.0f;

    int cx0 = min(max(ix0, 0), Ww - 1);
    int cx1 = min(max(ix1, 0), Ww - 1);
    int cy0 = min(max(iy0, 0), Hh - 1);
    int cy1 = min(max(iy1, 0), Hh - 1);
    int cz0 = min(max(iz0, 0), Dd - 1);
    int cz1 = min(max(iz1, 0), Dd - 1);

    int oz0 = cz0 * HW, oz1 = cz1 * HW;
    int oy0 = cy0 * Ww, oy1 = cy1 * Ww;

    c.o[0] = oz0 + oy0 + cx0;
    c.o[1] = oz0 + oy0 + cx1;
    c.o[2] = oz0 + oy1 + cx0;
    c.o[3] = oz0 + oy1 + cx1;
    c.o[4] = oz1 + oy0 + cx0;
    c.o[5] = oz1 + oy0 + cx1;
    c.o[6] = oz1 + oy1 + cx0;
    c.o[7] = oz1 + oy1 + cx1;

    float wz0y0 = wz0 * wy0;
    float wz0y1 = wz0 * wy1;
    float wz1y0 = wz1 * wy0;
    float wz1y1 = wz1 * wy1;

    c.w[0] = wz0y0 * wx0;
    c.w[1] = wz0y0 * wx1;
    c.w[2] = wz0y1 * wx0;
    c.w[3] = wz0y1 * wx1;
    c.w[4] = wz1y0 * wx0;
    c.w[5] = wz1y0 * wx1;
    c.w[6] = wz1y1 * wx0;
    c.w[7] = wz1y1 * wx1;
    return c;
}

__global__ __launch_bounds__(256) void st_kernel(
    const float* __restrict__ flow,  // [B, 3, D, H, W]
    float* __restrict__ out)         // [B, C, D, H, W]
{
    constexpr int NV = NVv;
    constexpr int NT = NV / 2;       // thread handles a y-pair, both batches

    int t = blockIdx.x * blockDim.x + threadIdx.x;
    if (t >= NT) return;

    int x  = t % Ww;
    int r  = t / Ww;
    int yh = r % (Hh / 2);
    int z  = r / (Hh / 2);
    int y  = yh * 2;

    int v0 = (z * Hh + y) * Ww + x;   // voxel for (z, y, x); y-pair partner at +Ww

    float res[2][2][2];               // [batch][voxel-in-pair][channel]

#pragma unroll
    for (int b = 0; b < 2; ++b) {
        const __half2* s = g_srcI + (size_t)b * NV;
#pragma unroll
        for (int k = 0; k < 2; ++k) {
            int v = v0 + k * Ww;
            const float* f = flow + b * (3 * NV) + v;
            float fx = __ldg(f);
            float fy = __ldg(f + NV);
            float fz = __ldg(f + 2 * NV);

            Corners c = make_corners(x, y + k, z, fx, fy, fz);

            __half2 h[8];
#pragma unroll
            for (int i = 0; i < 8; ++i) h[i] = __ldg(s + c.o[i]);

            float a0 = 0.f, a1 = 0.f;
#pragma unroll
            for (int i = 0; i < 8; ++i) {
                float2 e = __half22float2(h[i]);
                a0 = fmaf(c.w[i], e.x, a0);
                a1 = fmaf(c.w[i], e.y, a1);
            }
            res[b][k][0] = a0;
            res[b][k][1] = a1;
        }
    }

#pragma unroll
    for (int b = 0; b < 2; ++b)
#pragma unroll
        for (int ch = 0; ch < 2; ++ch) {
            float* obase = out + ((size_t)b * Cc + ch) * NV + v0;
            obase[0]  = res[b][0][ch];
            obase[Ww] = res[b][1][ch];
        }
}

extern "C" void kernel_launch(void* const* d_in, const int* in_sizes, int n_in,
                              void* d_out, int out_size) {
    const float* src  = (const float*)d_in[0];
    const float* flow = (const float*)d_in[1];
    float* out = (float*)d_out;

    int threads = 256;

    constexpr int NTOT = Bb * NVv;
    int blocks_pre = (NTOT / 4 + threads - 1) / threads;
    interleave_kernel<<<blocks_pre, threads>>>(src);

    constexpr int NT = NVv / 2;
    int blocks = (NT + threads - 1) / threads;
    st_kernel<<<blocks, threads>>>(flow, out);
}